// round 2
// baseline (speedup 1.0000x reference)
#include <cuda_runtime.h>
#include <cfloat>

// Problem constants
#define B_   4
#define C_   84
#define CP_  80        // channels used for the max (points[:, :-4])
#define H_   512
#define W_   512
#define HW_  (H_ * W_)        // 262144
#define W4_  (W_ / 4)         // 128
#define HW4_ (HW_ / 4)        // 65536
#define NROWS (B_ * H_)       // 2048

#define THREADS 512
#define TILE_FLOATS (C_ * W_)           // 43008
#define SMEM_FLOATS (TILE_FLOATS + 4 * W_)
#define SMEM_BYTES  (SMEM_FLOATS * 4)   // 180224

// Global scratch: probs rows + per-row ready flags
__device__ float g_probs[NROWS * W_];
__device__ int   g_flags[NROWS];

__device__ __forceinline__ int ld_acquire(const int* p) {
    int v;
    asm volatile("ld.acquire.gpu.s32 %0, [%1];" : "=r"(v) : "l"(p));
    return v;
}
__device__ __forceinline__ void st_release(int* p, int v) {
    asm volatile("st.release.gpu.s32 [%0], %1;" :: "l"(p), "r"(v));
}

__global__ void clear_flags_kernel() {
    int t = blockIdx.x * blockDim.x + threadIdx.x;
    if (t < NROWS) g_flags[t] = 0;
}

// ---------------------------------------------------------------------------
// Fused kernel: one CTA per (b, row).
//  A) load 84ch x 512cols into smem (points read ONCE)
//  B) probs row = max over first 80 channels; publish to g_probs + flag
//  C) acquire-wait neighbor rows, build 3x3 NMS mask
//  D) multiply smem tile by mask, stream to out
// ---------------------------------------------------------------------------
__global__ __launch_bounds__(THREADS, 1) void nms_fused_kernel(
    const float* __restrict__ pts, float* __restrict__ out) {
    extern __shared__ float sm[];
    float* tile   = sm;                     // [C_][W_]
    float* mid_s  = sm + TILE_FLOATS;       // [W_]
    float* up_s   = mid_s + W_;             // [W_]
    float* dn_s   = up_s + W_;              // [W_]
    float* mask_s = dn_s + W_;              // [W_]

    const int tid = threadIdx.x;
    const int r   = blockIdx.x;             // global row id: b*H + i
    const int b   = r >> 9;                 // / 512
    const int i   = r & (H_ - 1);

    // ---- Phase A: cooperative load of the whole (84 x 512) tile ----
    const float4* src4 = reinterpret_cast<const float4*>(pts)
                       + (size_t)b * C_ * HW4_ + (size_t)i * W4_;
    float4* tile4 = reinterpret_cast<float4*>(tile);
    #pragma unroll
    for (int idx = tid; idx < C_ * W4_; idx += THREADS) {
        int c = idx >> 7;                   // / 128
        int j = idx & (W4_ - 1);
        tile4[idx] = src4[(size_t)c * HW4_ + j];
    }
    __syncthreads();

    // ---- Phase B: probs (channel max over first 80) + publish ----
    {
        int w = tid;
        float p = tile[w];
        #pragma unroll 8
        for (int c = 1; c < CP_; c++) p = fmaxf(p, tile[c * W_ + w]);
        mid_s[w] = p;
        g_probs[(size_t)r * W_ + w] = p;
    }
    __threadfence();
    __syncthreads();
    if (tid == 0) st_release(&g_flags[r], 1);

    // ---- Phase C: wait for neighbor rows, load halo, build mask ----
    if (i > 0) {
        const int* f = &g_flags[r - 1];
        while (ld_acquire(f) == 0) __nanosleep(64);
        up_s[tid] = g_probs[(size_t)(r - 1) * W_ + tid];
    } else {
        up_s[tid] = 0.0f;
    }
    if (i < H_ - 1) {
        const int* f = &g_flags[r + 1];
        while (ld_acquire(f) == 0) __nanosleep(64);
        dn_s[tid] = g_probs[(size_t)(r + 1) * W_ + tid];
    } else {
        dn_s[tid] = 0.0f;
    }
    __syncthreads();

    {
        int w = tid;
        float p  = mid_s[w];
        float ul = (w > 0)      ? up_s[w - 1]  : 0.0f;
        float uc =                up_s[w];
        float ur = (w < W_ - 1) ? up_s[w + 1]  : 0.0f;
        float ml = (w > 0)      ? mid_s[w - 1] : 0.0f;
        float mr = (w < W_ - 1) ? mid_s[w + 1] : 0.0f;
        float dl = (w > 0)      ? dn_s[w - 1]  : 0.0f;
        float dc =                dn_s[w];
        float dr = (w < W_ - 1) ? dn_s[w + 1]  : 0.0f;
        // strict > for neighbors before center (up row, mid-left),
        // >= for after (mid-right, down row); OOB = 0 (zero pad)
        bool ok = (p >  ul) & (p >  uc) & (p >  ur)
                & (p >  ml) & (p >= mr)
                & (p >= dl) & (p >= dc) & (p >= dr);
        mask_s[w] = ok ? 1.0f : 0.0f;
    }
    __syncthreads();

    // ---- Phase D: multiply & stream out ----
    float4* dst4 = reinterpret_cast<float4*>(out)
                 + (size_t)b * C_ * HW4_ + (size_t)i * W4_;
    const float4* mask4 = reinterpret_cast<const float4*>(mask_s);
    #pragma unroll
    for (int idx = tid; idx < C_ * W4_; idx += THREADS) {
        int c = idx >> 7;
        int j = idx & (W4_ - 1);
        float4 v = tile4[idx];
        float4 m = mask4[j];
        v.x *= m.x; v.y *= m.y; v.z *= m.z; v.w *= m.w;
        dst4[(size_t)c * HW4_ + j] = v;
    }
}

extern "C" void kernel_launch(void* const* d_in, const int* in_sizes, int n_in,
                              void* d_out, int out_size) {
    const float* pts = (const float*)d_in[0];
    float* out = (float*)d_out;

    cudaFuncSetAttribute(nms_fused_kernel,
                         cudaFuncAttributeMaxDynamicSharedMemorySize, SMEM_BYTES);

    clear_flags_kernel<<<(NROWS + 511) / 512, 512>>>();
    nms_fused_kernel<<<NROWS, THREADS, SMEM_BYTES>>>(pts, out);
}

// round 3
// speedup vs baseline: 1.3030x; 1.3030x over previous
#include <cuda_runtime.h>
#include <cstdint>

// Problem constants
#define B_   4
#define C_   84
#define CP_  80        // channels used for the max (points[:, :-4])
#define H_   512
#define W_   512
#define HW_  (H_ * W_)        // 262144
#define NROWS (B_ * H_)       // 2048

#define QCOLS   128                       // columns per CTA tile (quarter row)
#define NQ      4                         // quarters per row
#define THREADS 128
#define TILE_BYTES (C_ * QCOLS * 4)       // 43008
#define SEG_BYTES  (QCOLS * 4)            // 512 contiguous bytes per channel

// Global scratch: probs rows + per-row "quarters published" counters
__device__ float g_probs[NROWS * W_];
__device__ int   g_flags[NROWS];

__device__ __forceinline__ int ld_acquire(const int* p) {
    int v;
    asm volatile("ld.acquire.gpu.s32 %0, [%1];" : "=r"(v) : "l"(p));
    return v;
}
__device__ __forceinline__ uint32_t smem_u32(const void* p) {
    uint32_t a;
    asm("{ .reg .u64 t; cvta.to.shared.u64 t, %1; cvt.u32.u64 %0, t; }"
        : "=r"(a) : "l"(p));
    return a;
}

__global__ void clear_flags_kernel() {
    int t = blockIdx.x * blockDim.x + threadIdx.x;
    if (t < NROWS) g_flags[t] = 0;
}

// ---------------------------------------------------------------------------
// Fused NMS kernel. One CTA per (row, quarter): tile = 84 ch x 128 cols.
//  A) bulk-DMA the tile into smem (points read ONCE)
//  B) probs = channel-max over first 80; publish to g_probs; count up row flag
//  C) wait rows r-1, r, r+1 fully published; build 3x3 NMS mask
//  D) multiply tile by mask in smem; bulk-DMA tile to out
// ---------------------------------------------------------------------------
__global__ __launch_bounds__(THREADS) void nms_fused_kernel(
    const float* __restrict__ pts, float* __restrict__ out) {
    __shared__ __align__(128) float tile[C_ * QCOLS];      // 42 KB
    __shared__ __align__(16)  float up_s[QCOLS + 2];
    __shared__ __align__(16)  float mid_s[QCOLS + 2];
    __shared__ __align__(16)  float dn_s[QCOLS + 2];
    __shared__ __align__(16)  float mask_s[QCOLS];
    __shared__ __align__(8)   uint64_t mbar;

    const int tid = threadIdx.x;
    const int cta = blockIdx.x;
    const int r   = cta >> 2;              // row id: b*H + i
    const int q   = cta & 3;               // quarter
    const int b   = r >> 9;
    const int i   = r & (H_ - 1);
    const int c0  = q * QCOLS;             // first global column of this tile

    const uint32_t mbar_a = smem_u32(&mbar);
    const uint32_t tile_a = smem_u32(tile);

    // ---- Phase A: bulk async load, 84 x 512B contiguous segments ----
    if (tid == 0) {
        asm volatile("mbarrier.init.shared.b64 [%0], 1;" :: "r"(mbar_a) : "memory");
        asm volatile("mbarrier.arrive.expect_tx.shared.b64 _, [%0], %1;"
                     :: "r"(mbar_a), "r"((uint32_t)TILE_BYTES) : "memory");
    }
    __syncthreads();
    if (tid < C_) {
        const char* src = (const char*)pts
            + ((size_t)(b * C_ + tid) * HW_ + (size_t)i * W_ + c0) * 4;
        asm volatile(
            "cp.async.bulk.shared::cta.global.mbarrier::complete_tx::bytes "
            "[%0], [%1], %2, [%3];"
            :: "r"(tile_a + tid * SEG_BYTES), "l"(src), "r"((uint32_t)SEG_BYTES),
               "r"(mbar_a) : "memory");
    }
    // wait for DMA completion (phase parity 0; mbarrier used once per launch)
    {
        uint32_t done;
        asm volatile(
            "{ .reg .pred p; mbarrier.try_wait.parity.shared.b64 p, [%1], 0; "
            "selp.b32 %0, 1, 0, p; }" : "=r"(done) : "r"(mbar_a) : "memory");
        while (!done) {
            asm volatile(
                "{ .reg .pred p; mbarrier.try_wait.parity.shared.b64 p, [%1], 0, 0x989680; "
                "selp.b32 %0, 1, 0, p; }" : "=r"(done) : "r"(mbar_a) : "memory");
        }
    }
    __syncthreads();

    // ---- Phase B: probs for my 128 columns + publish ----
    {
        float p = tile[tid];
        #pragma unroll 10
        for (int c = 1; c < CP_; c++) p = fmaxf(p, tile[c * QCOLS + tid]);
        g_probs[(size_t)r * W_ + c0 + tid] = p;
    }
    __threadfence();
    __syncthreads();
    if (tid == 0) atomicAdd(&g_flags[r], 1);

    // ---- Phase C: wait for full rows r-1, r, r+1; build halo + mask ----
    if (tid == 0) {                        // own row (boundary cols from peers)
        const int* f = &g_flags[r];
        while (ld_acquire(f) < NQ) __nanosleep(32);
    }
    if (tid == 32 && i > 0) {
        const int* f = &g_flags[r - 1];
        while (ld_acquire(f) < NQ) __nanosleep(32);
    }
    if (tid == 64 && i < H_ - 1) {
        const int* f = &g_flags[r + 1];
        while (ld_acquire(f) < NQ) __nanosleep(32);
    }
    __syncthreads();

    for (int idx = tid; idx < QCOLS + 2; idx += THREADS) {
        int gcol = c0 - 1 + idx;
        bool cok = (gcol >= 0) & (gcol < W_);
        up_s[idx]  = (cok && i > 0)      ? g_probs[(size_t)(r - 1) * W_ + gcol] : 0.0f;
        mid_s[idx] =  cok                ? g_probs[(size_t)r       * W_ + gcol] : 0.0f;
        dn_s[idx]  = (cok && i < H_ - 1) ? g_probs[(size_t)(r + 1) * W_ + gcol] : 0.0f;
    }
    __syncthreads();

    {
        int w = tid;
        float p = mid_s[w + 1];
        // strict > for neighbors before center (up row, mid-left),
        // >= for after (mid-right, down row); OOB = 0 (zero padding)
        bool ok = (p >  up_s[w]) & (p >  up_s[w + 1]) & (p >  up_s[w + 2])
                & (p >  mid_s[w]) & (p >= mid_s[w + 2])
                & (p >= dn_s[w]) & (p >= dn_s[w + 1]) & (p >= dn_s[w + 2]);
        mask_s[w] = ok ? 1.0f : 0.0f;
    }
    __syncthreads();

    // ---- Phase D: multiply in smem, bulk async store ----
    {
        float m = mask_s[tid];
        #pragma unroll 12
        for (int c = 0; c < C_; c++) tile[c * QCOLS + tid] *= m;
    }
    __syncthreads();
    asm volatile("fence.proxy.async.shared::cta;" ::: "memory");

    if (tid < C_) {
        char* dst = (char*)out
            + ((size_t)(b * C_ + tid) * HW_ + (size_t)i * W_ + c0) * 4;
        asm volatile(
            "cp.async.bulk.global.shared::cta.bulk_group [%0], [%1], %2;"
            :: "l"(dst), "r"(tile_a + tid * SEG_BYTES), "r"((uint32_t)SEG_BYTES)
            : "memory");
        asm volatile("cp.async.bulk.commit_group;" ::: "memory");
        asm volatile("cp.async.bulk.wait_group 0;" ::: "memory");
    }
}

extern "C" void kernel_launch(void* const* d_in, const int* in_sizes, int n_in,
                              void* d_out, int out_size) {
    const float* pts = (const float*)d_in[0];
    float* out = (float*)d_out;

    clear_flags_kernel<<<(NROWS + 511) / 512, 512>>>();
    nms_fused_kernel<<<NROWS * NQ, THREADS>>>(pts, out);
}